// round 11
// baseline (speedup 1.0000x reference)
#include <cuda_runtime.h>
#include <math.h>

#define B 64
#define H 80
#define W 80
#define C 80
#define CP 84
#define K 100
#define JS 10            // columns per thread strip (W/JS = 8 strips)
#define BLOCKS_PER_B 50  // 12800 threads per batch / 256
#define HI_MAX 16384
#define LO_MAX 131072
#define NBINS 4096       // key>>19; positive float keys < 0x7F800000 -> bin < 4081
#define EQCAP 1024
#define CUTOFF_BITS 0x40200000u   // __float_as_uint(2.5f); key > bits <=> score > 2.5

// pk = (float_bits(score) << 32) | ~sidx : plain u64 '>' == (score desc, idx asc),
// matching jax stable argsort of -score.
__device__ unsigned long long g_hi[B][HI_MAX];
__device__ unsigned long long g_lo[B][LO_MAX];
__device__ unsigned long long g_pcnt[B * 16];   // packed (hi<<32 | lo), 128B stride
__device__ int g_done[B * 32];                  // finished-block counters, padded

__device__ __forceinline__ float4 max4(float4 a, float4 b) {
    return make_float4(fmaxf(a.x, b.x), fmaxf(a.y, b.y),
                       fmaxf(a.z, b.z), fmaxf(a.w, b.w));
}

// ---------------------------------------------------------------------------
// Select for one batch, run by the LAST finished block of that batch.
// 256 threads. smem arrays passed in from kernel scope.
__device__ void do_select(int b, const float* __restrict__ y, float* __restrict__ out,
                          int* hist, unsigned long long* se, unsigned long long* a,
                          int* csums, int* s_scalars) {
    int tid = threadIdx.x;                      // 256
    int& s_tbin = s_scalars[0];
    int& s_cA   = s_scalars[1];
    int& s_cE   = s_scalars[2];

    unsigned long long cnts = g_pcnt[b * 16];
    int n_hi = (int)(cnts >> 32);         if (n_hi > HI_MAX) n_hi = HI_MAX;
    int n_lo = (int)(cnts & 0xffffffffu); if (n_lo > LO_MAX) n_lo = LO_MAX;
    bool use_lo = (n_hi < K);                   // exact fallback
    int n2 = use_lo ? n_lo : 0;

    const unsigned long long* hi = g_hi[b];
    const unsigned long long* lo = g_lo[b];

    #pragma unroll
    for (int i = tid; i < NBINS; i += 256) hist[i] = 0;
    if (tid == 0) { s_cA = 0; s_cE = 0; s_tbin = -1; }
    __syncthreads();

    // pass 1: histogram of key>>19 (pk>>51)
    for (int p = tid; p < n_hi; p += 256) atomicAdd(&hist[(int)(hi[p] >> 51)], 1);
    for (int p = tid; p < n2;   p += 256) atomicAdd(&hist[(int)(lo[p] >> 51)], 1);
    __syncthreads();

    {
        int s = 0, base = tid * (NBINS / 256);
        #pragma unroll
        for (int q = 0; q < NBINS / 256; ++q) s += hist[base + q];
        csums[tid] = s;
    }
    __syncthreads();

    // parallel threshold: warp 0, 32 segments of 8 csums
    if (tid < 32) {
        int seg = 0, base = tid * 8;
        #pragma unroll
        for (int q = 0; q < 8; ++q) seg += csums[base + q];
        int x = seg;
        #pragma unroll
        for (int d = 1; d < 32; d <<= 1) {
            int o = __shfl_down_sync(0xffffffffu, x, d);
            if (tid + d < 32) x += o;
        }
        int suf_excl = x - seg;                  // total in segments above mine
        if (suf_excl < K && suf_excl + seg >= K) {
            int acc = suf_excl;
            for (int c = base + 7; c >= base; --c) {
                int h = csums[c];
                if (acc + h >= K) {
                    for (int q = (c + 1) * (NBINS / 256) - 1; q >= c * (NBINS / 256); --q) {
                        int hb2 = hist[q];
                        if (acc + hb2 >= K) { s_tbin = q; break; }
                        acc += hb2;
                    }
                    break;
                }
                acc += h;
            }
        }
    }
    __syncthreads();
    int tb = s_tbin;                             // -1 => total < K: take everything

    // pass 2: compact into above-list (<K) and tie-list
    for (int seg = 0; seg < 2; ++seg) {
        const unsigned long long* src = seg ? lo : hi;
        int n = seg ? n2 : n_hi;
        for (int p = tid; p < n; p += 256) {
            unsigned long long pk = src[p];
            int bin = (int)(pk >> 51);
            if (bin > tb) {
                int q = atomicAdd(&s_cA, 1);
                if (q < K) a[q] = pk;
            } else if (bin == tb) {
                int q = atomicAdd(&s_cE, 1);
                if (q < EQCAP) se[q] = pk;
            }
        }
    }
    __syncthreads();

    int mA = s_cA; if (mA > K) mA = K;
    int nE = s_cE; if (nE > EQCAP) nE = EQCAP;
    int take = K - mA; if (take > nE) take = nE;

    // ties: top 'take' by (score desc, idx asc) == largest packed
    for (int e = tid; e < nE; e += 256) {
        unsigned long long mine = se[e];
        int r = 0;
        for (int q = 0; q < nE; ++q) r += (se[q] > mine) ? 1 : 0;
        if (r < take) a[mA + r] = mine;
    }
    __syncthreads();

    int M = mA + take;                           // == K normally

    float* score_out = out;
    float* k_out     = out + B * K;
    float* c_out     = out + 2 * B * K;
    float* w_out     = out + 4 * B * K;

    if (tid < M) {
        unsigned long long mine = a[tid];
        int r = 0;
        for (int q = 0; q < M; ++q) r += (a[q] > mine) ? 1 : 0;

        int fi  = (int)(~(unsigned)(mine & 0xffffffffu));
        float sc = __uint_as_float((unsigned)(mine >> 32));
        int kk  = fi % C;
        int rem = fi / C;
        int jj  = rem % W;
        int ii  = rem / W;
        const float* p = y + ((size_t)((b * H + ii) * W + jj)) * CP;
        float whx = 4.0f * (expf(p[C])     - 1.0f);
        float why = 4.0f * (expf(p[C + 1]) - 1.0f);
        float cx  = 4.0f * (float)jj + p[C + 2];
        float cy  = 4.0f * (float)ii + p[C + 3];

        score_out[b * K + r] = sc;
        k_out[b * K + r]     = (float)kk;
        c_out[(b * K + r) * 2 + 0] = cx;
        c_out[(b * K + r) * 2 + 1] = cy;
        w_out[(b * K + r) * 2 + 0] = whx;
        w_out[(b * K + r) * 2 + 1] = why;
    }

    for (int r = M + tid; r < K; r += 256) {     // degenerate pad only
        score_out[b * K + r] = 0.0f;
        k_out[b * K + r]     = 0.0f;
        c_out[(b * K + r) * 2 + 0] = 0.0f;
        c_out[(b * K + r) * 2 + 1] = 0.0f;
        w_out[(b * K + r) * 2 + 0] = 0.0f;
        w_out[(b * K + r) * 2 + 1] = 0.0f;
    }

    // reset per-replay state
    __syncthreads();
    if (tid == 0) { g_pcnt[b * 16] = 0ull; g_done[b * 32] = 0; }
}

// ---------------------------------------------------------------------------
// Fused kernel: 3x3 NMS peaks (sliding window along j, 4 ch x 1 row x JS cols
// per thread), then the LAST finished block of each batch runs select inline.
__global__ void __launch_bounds__(256) fused_kernel(const float* __restrict__ y,
                                                    float* __restrict__ out) {
    __shared__ int  s_hist[NBINS];               // 16KB (select phase)
    __shared__ unsigned long long s_se[EQCAP];   // 8KB  (select phase)
    __shared__ unsigned long long s_a[K];
    __shared__ int  s_csums[256];
    __shared__ int  s_scalars[3];
    __shared__ unsigned long long s_ret;
    __shared__ int  s_tot;
    __shared__ int  s_last;

    if (threadIdx.x == 0) s_tot = 0;
    __syncthreads();

    int t  = blockIdx.x * 256 + threadIdx.x;
    int cg = t % (C / 4);                      // fastest: 20
    int i  = (t / (C / 4)) % H;                // then row: 80
    int st = (t / ((C / 4) * H)) % (W / JS);   // then strip: 8
    int b  = t / ((C / 4) * H * (W / JS));
    int c0 = cg * 4;
    int j0 = st * JS;

    const float NEGF = __int_as_float(0xff800000);
    const float4 NEG4 = make_float4(NEGF, NEGF, NEGF, NEGF);
    const size_t rowS = (size_t)W * CP;
    const float* rowp = y + ((size_t)(b * H + i)) * rowS + c0;
    bool up = (i > 0), dn = (i < H - 1);

    unsigned long long cand[16];
    int nc = 0;

    float4 cma, cmb, cmc, cvb, cvc;

    {
        int jj = j0 - 1;
        if (jj >= 0) {
            const float* p = rowp + (size_t)jj * CP;
            float4 a = up ? *(const float4*)(p - rowS) : NEG4;
            float4 c = *(const float4*)p;
            float4 d = dn ? *(const float4*)(p + rowS) : NEG4;
            cma = max4(max4(a, d), c);
        } else cma = NEG4;
    }
    {
        const float* p = rowp + (size_t)j0 * CP;
        float4 a = up ? *(const float4*)(p - rowS) : NEG4;
        float4 c = *(const float4*)p;
        float4 d = dn ? *(const float4*)(p + rowS) : NEG4;
        cmb = max4(max4(a, d), c);
        cvb = c;
    }

    #pragma unroll
    for (int jo = 0; jo < JS; ++jo) {
        int j = j0 + jo;
        int jj = j + 1;
        if (jj < W) {
            const float* p = rowp + (size_t)jj * CP;
            float4 a = up ? *(const float4*)(p - rowS) : NEG4;
            float4 c = *(const float4*)p;
            float4 d = dn ? *(const float4*)(p + rowS) : NEG4;
            cmc = max4(max4(a, d), c);
            cvc = c;
        } else { cmc = NEG4; cvc = NEG4; }

        float4 mx = max4(max4(cma, cmc), cmb);
        float vr[4] = {cvb.x, cvb.y, cvb.z, cvb.w};
        float mr[4] = {mx.x, mx.y, mx.z, mx.w};
        int sidx = (i * W + j) * C + c0;
        #pragma unroll
        for (int q = 0; q < 4; ++q) {
            if (vr[q] == mr[q] && vr[q] > 0.0f) {
                unsigned key = __float_as_uint(vr[q]);
                if (nc < 16)
                    cand[nc] = ((unsigned long long)key << 32)
                             | (unsigned)(~(unsigned)(sidx + q));
                nc++;
            }
        }
        cma = cmb; cmb = cmc; cvb = cvc;
    }
    if (nc > 16) nc = 16;

    int cnt_hi = 0;
    for (int q = 0; q < nc; ++q)
        cnt_hi += ((unsigned)(cand[q] >> 32) > CUTOFF_BITS) ? 1 : 0;
    int cnt_lo = nc - cnt_hi;

    // packed warp prefix + ONE packed u64 atomic per block
    int lane = threadIdx.x & 31;
    int packed = (cnt_hi << 16) | cnt_lo;
    int incl = packed;
    #pragma unroll
    for (int d = 1; d < 32; d <<= 1) {
        int o = __shfl_up_sync(0xffffffffu, incl, d);
        if (lane >= d) incl += o;
    }
    int wtot = __shfl_sync(0xffffffffu, incl, 31);
    int wbase = 0;
    if (lane == 31 && wtot > 0) wbase = atomicAdd(&s_tot, wtot);
    wbase = __shfl_sync(0xffffffffu, wbase, 31);
    __syncthreads();
    if (threadIdx.x == 0) {
        int bt = s_tot;
        unsigned long long add =
            ((unsigned long long)(unsigned)(bt >> 16) << 32) | (unsigned)(bt & 0xffff);
        s_ret = (bt != 0) ? atomicAdd(&g_pcnt[b * 16], add) : 0ull;
    }
    __syncthreads();

    if (nc > 0) {
        unsigned long long ret = s_ret;
        int excl = (wbase + incl - packed);
        int off_hi = (int)(ret >> 32) + (excl >> 16);
        int off_lo = (int)(ret & 0xffffffffu) + (excl & 0xffff);
        for (int q = 0; q < nc; ++q) {
            unsigned long long pk = cand[q];
            if ((unsigned)(pk >> 32) > CUTOFF_BITS) {
                if (off_hi < HI_MAX) g_hi[b][off_hi] = pk;
                off_hi++;
            } else {
                if (off_lo < LO_MAX) g_lo[b][off_lo] = pk;
                off_lo++;
            }
        }
    }

    // last finished block of this batch runs select
    __threadfence();
    __syncthreads();
    if (threadIdx.x == 0) {
        int d = atomicAdd(&g_done[b * 32], 1);
        s_last = (d == BLOCKS_PER_B - 1) ? 1 : 0;
    }
    __syncthreads();
    if (s_last) {
        __threadfence();   // acquire side: see all other blocks' candidate writes
        do_select(b, y, out, s_hist, s_se, s_a, s_csums, s_scalars);
    }
}

extern "C" void kernel_launch(void* const* d_in, const int* in_sizes, int n_in,
                              void* d_out, int out_size) {
    const float* yp = (const float*)d_in[0];
    float* out = (float*)d_out;

    int total = B * H * (W / JS) * (C / 4);      // 819,200 threads
    fused_kernel<<<total / 256, 256>>>(yp, out);
}

// round 12
// speedup vs baseline: 1.2622x; 1.2622x over previous
#include <cuda_runtime.h>
#include <math.h>

#define B 64
#define H 80
#define W 80
#define C 80
#define CP 84
#define K 100
#define JS 5             // columns per thread strip (W/JS = 16 strips)
#define VR 2             // rows per thread (H/VR = 40)
#define HI_MAX 16384
#define LO_MAX 131072
#define NBINS 4096       // key>>19; positive float keys < 0x7F800000 -> bin < 4081
#define EQCAP 1024
#define CUTOFF_BITS 0x40200000u   // __float_as_uint(2.5f); key > bits <=> score > 2.5

// pk = (float_bits(score) << 32) | ~sidx : plain u64 '>' == (score desc, idx asc),
// matching jax stable argsort of -score.
__device__ unsigned long long g_hi[B][HI_MAX];
__device__ unsigned long long g_lo[B][LO_MAX];
__device__ unsigned long long g_pcnt[B * 16];   // packed (hi<<32 | lo), 128B stride

__device__ __forceinline__ float4 max4(float4 a, float4 b) {
    return make_float4(fmaxf(a.x, b.x), fmaxf(a.y, b.y),
                       fmaxf(a.z, b.z), fmaxf(a.w, b.w));
}

// ---------------------------------------------------------------------------
// K1: 3x3 NMS peaks, sliding window along j, 2 rows per thread.
// One thread = 4 channels x 2 rows x JS columns. Per column step: 4 row loads
// (i0-1..i0+2) -> two vertical 3-maxes -> 2x4 outputs. 28 loads / 40 values.
// Index order (cg, iq, st, b): block covers ~25 consecutive rows of ONE strip
// so vertical row reuse between neighboring threads hits L1.
// threads = B * 20 * 40 * 16 = 819,200; blocks uniform in b.
__global__ void __launch_bounds__(256) peaks_kernel(const float* __restrict__ y) {
    __shared__ unsigned long long s_ret;
    __shared__ int s_tot;      // packed hi<<16 | lo
    if (threadIdx.x == 0) s_tot = 0;
    __syncthreads();

    int t  = blockIdx.x * 256 + threadIdx.x;
    int cg = t % 20;                       // fastest
    int iq = (t / 20) % (H / VR);          // row pair
    int st = (t / (20 * (H / VR))) % (W / JS);
    int b  = t / (20 * (H / VR) * (W / JS));
    int c0 = cg * 4;
    int i0 = iq * VR;
    int j0 = st * JS;

    const float NEGF = __int_as_float(0xff800000);
    const float4 NEG4 = make_float4(NEGF, NEGF, NEGF, NEGF);
    const size_t rowS = (size_t)W * CP;
    const float* bbase = y + (size_t)b * H * rowS + c0;
    bool up = (i0 > 0), dn = (i0 + VR < H);

    const float* p0 = bbase + (size_t)(i0 - 1) * rowS;  // row above (may be OOB; guarded)
    const float* p1 = bbase + (size_t)i0 * rowS;
    const float* p2 = bbase + (size_t)(i0 + 1) * rowS;
    const float* p3 = bbase + (size_t)(i0 + 2) * rowS;  // row below pair (guarded)

    unsigned long long cand[16];
    int nc = 0;

    // sliding state: vertical maxes (vm) and center values (cv) for 2 rows
    float4 cma0, cma1, cmb0, cmb1, cmc0, cmc1;
    float4 cvb0, cvb1, cvc0, cvc1;

    // column j0-1
    {
        int jj = j0 - 1;
        if (jj >= 0) {
            size_t o = (size_t)jj * CP;
            float4 a  = up ? *(const float4*)(p0 + o) : NEG4;
            float4 r1 = *(const float4*)(p1 + o);
            float4 r2 = *(const float4*)(p2 + o);
            float4 d  = dn ? *(const float4*)(p3 + o) : NEG4;
            cma0 = max4(max4(a, r1), r2);
            cma1 = max4(max4(r1, r2), d);
        } else { cma0 = NEG4; cma1 = NEG4; }
    }
    // column j0
    {
        size_t o = (size_t)j0 * CP;
        float4 a  = up ? *(const float4*)(p0 + o) : NEG4;
        float4 r1 = *(const float4*)(p1 + o);
        float4 r2 = *(const float4*)(p2 + o);
        float4 d  = dn ? *(const float4*)(p3 + o) : NEG4;
        cmb0 = max4(max4(a, r1), r2);
        cmb1 = max4(max4(r1, r2), d);
        cvb0 = r1; cvb1 = r2;
    }

    #pragma unroll
    for (int jo = 0; jo < JS; ++jo) {
        int j = j0 + jo;
        int jj = j + 1;
        if (jj < W) {
            size_t o = (size_t)jj * CP;
            float4 a  = up ? *(const float4*)(p0 + o) : NEG4;
            float4 r1 = *(const float4*)(p1 + o);
            float4 r2 = *(const float4*)(p2 + o);
            float4 d  = dn ? *(const float4*)(p3 + o) : NEG4;
            cmc0 = max4(max4(a, r1), r2);
            cmc1 = max4(max4(r1, r2), d);
            cvc0 = r1; cvc1 = r2;
        } else { cmc0 = NEG4; cmc1 = NEG4; cvc0 = NEG4; cvc1 = NEG4; }

        // row 0 of pair
        {
            float4 mx = max4(max4(cma0, cmc0), cmb0);
            float vr4[4] = {cvb0.x, cvb0.y, cvb0.z, cvb0.w};
            float mr4[4] = {mx.x, mx.y, mx.z, mx.w};
            int sidx = (i0 * W + j) * C + c0;
            #pragma unroll
            for (int q = 0; q < 4; ++q) {
                if (vr4[q] == mr4[q] && vr4[q] > 0.0f) {
                    unsigned key = __float_as_uint(vr4[q]);
                    if (nc < 16)
                        cand[nc] = ((unsigned long long)key << 32)
                                 | (unsigned)(~(unsigned)(sidx + q));
                    nc++;
                }
            }
        }
        // row 1 of pair
        {
            float4 mx = max4(max4(cma1, cmc1), cmb1);
            float vr4[4] = {cvb1.x, cvb1.y, cvb1.z, cvb1.w};
            float mr4[4] = {mx.x, mx.y, mx.z, mx.w};
            int sidx = ((i0 + 1) * W + j) * C + c0;
            #pragma unroll
            for (int q = 0; q < 4; ++q) {
                if (vr4[q] == mr4[q] && vr4[q] > 0.0f) {
                    unsigned key = __float_as_uint(vr4[q]);
                    if (nc < 16)
                        cand[nc] = ((unsigned long long)key << 32)
                                 | (unsigned)(~(unsigned)(sidx + q));
                    nc++;
                }
            }
        }

        cma0 = cmb0; cma1 = cmb1;
        cmb0 = cmc0; cmb1 = cmc1;
        cvb0 = cvc0; cvb1 = cvc1;
    }
    if (nc > 16) nc = 16;

    int cnt_hi = 0;
    for (int q = 0; q < nc; ++q)
        cnt_hi += ((unsigned)(cand[q] >> 32) > CUTOFF_BITS) ? 1 : 0;
    int cnt_lo = nc - cnt_hi;

    // packed warp prefix + ONE packed u64 atomic per block
    int lane = threadIdx.x & 31;
    int packed = (cnt_hi << 16) | cnt_lo;
    int incl = packed;
    #pragma unroll
    for (int d = 1; d < 32; d <<= 1) {
        int o = __shfl_up_sync(0xffffffffu, incl, d);
        if (lane >= d) incl += o;
    }
    int wtot = __shfl_sync(0xffffffffu, incl, 31);
    int wbase = 0;
    if (lane == 31 && wtot > 0) wbase = atomicAdd(&s_tot, wtot);
    wbase = __shfl_sync(0xffffffffu, wbase, 31);
    __syncthreads();
    if (threadIdx.x == 0) {
        int bt = s_tot;
        unsigned long long add =
            ((unsigned long long)(unsigned)(bt >> 16) << 32) | (unsigned)(bt & 0xffff);
        s_ret = (bt != 0) ? atomicAdd(&g_pcnt[b * 16], add) : 0ull;
    }
    __syncthreads();

    if (nc > 0) {
        unsigned long long ret = s_ret;
        int excl = (wbase + incl - packed);
        int off_hi = (int)(ret >> 32) + (excl >> 16);
        int off_lo = (int)(ret & 0xffffffffu) + (excl & 0xffff);
        for (int q = 0; q < nc; ++q) {
            unsigned long long pk = cand[q];
            if ((unsigned)(pk >> 32) > CUTOFF_BITS) {
                if (off_hi < HI_MAX) g_hi[b][off_hi] = pk;
                off_hi++;
            } else {
                if (off_lo < LO_MAX) g_lo[b][off_lo] = pk;
                off_lo++;
            }
        }
    }
}

// ---------------------------------------------------------------------------
// K2: one block per batch: smem histogram -> exact K-th threshold bin ->
// compact (> and ==) -> exact rank -> gather -> emit. Normally only the
// small hi list is scanned; exact fallback to hi+lo if n_hi < K.
__global__ void __launch_bounds__(512) select_kernel(const float* __restrict__ y,
                                                     float* __restrict__ out) {
    __shared__ int hist[NBINS];                 // 16KB
    __shared__ unsigned long long se[EQCAP];    // 8KB
    __shared__ unsigned long long a[K];
    __shared__ int csums[512];
    __shared__ int s_tbin, s_cA, s_cE;

    int b   = blockIdx.x;
    int tid = threadIdx.x;                      // 512
    unsigned long long cnts = g_pcnt[b * 16];
    int n_hi = (int)(cnts >> 32);         if (n_hi > HI_MAX) n_hi = HI_MAX;
    int n_lo = (int)(cnts & 0xffffffffu); if (n_lo > LO_MAX) n_lo = LO_MAX;
    bool use_lo = (n_hi < K);                   // exact fallback
    int n2 = use_lo ? n_lo : 0;

    const unsigned long long* hi = g_hi[b];
    const unsigned long long* lo = g_lo[b];

    #pragma unroll
    for (int i = tid; i < NBINS; i += 512) hist[i] = 0;
    if (tid == 0) { s_cA = 0; s_cE = 0; s_tbin = -1; }
    __syncthreads();

    // pass 1: histogram of key>>19 (pk>>51)
    for (int p = tid; p < n_hi; p += 512) atomicAdd(&hist[(int)(hi[p] >> 51)], 1);
    for (int p = tid; p < n2;   p += 512) atomicAdd(&hist[(int)(lo[p] >> 51)], 1);
    __syncthreads();

    {
        int s = 0, base = tid * (NBINS / 512);
        #pragma unroll
        for (int q = 0; q < NBINS / 512; ++q) s += hist[base + q];
        csums[tid] = s;
    }
    __syncthreads();

    // parallel threshold: warp 0, 32 segments of 16 csums
    if (tid < 32) {
        int seg = 0, base = tid * 16;
        #pragma unroll
        for (int q = 0; q < 16; ++q) seg += csums[base + q];
        int x = seg;
        #pragma unroll
        for (int d = 1; d < 32; d <<= 1) {
            int o = __shfl_down_sync(0xffffffffu, x, d);
            if (tid + d < 32) x += o;
        }
        int suf_excl = x - seg;                  // total in segments above mine
        if (suf_excl < K && suf_excl + seg >= K) {
            int acc = suf_excl;
            for (int c = base + 15; c >= base; --c) {
                int h = csums[c];
                if (acc + h >= K) {
                    for (int q = (c + 1) * (NBINS / 512) - 1; q >= c * (NBINS / 512); --q) {
                        int hb2 = hist[q];
                        if (acc + hb2 >= K) { s_tbin = q; break; }
                        acc += hb2;
                    }
                    break;
                }
                acc += h;
            }
        }
    }
    __syncthreads();
    int tb = s_tbin;                             // -1 => total < K: take everything

    // pass 2: compact into above-list (<K) and tie-list
    for (int seg = 0; seg < 2; ++seg) {
        const unsigned long long* src = seg ? lo : hi;
        int n = seg ? n2 : n_hi;
        for (int p = tid; p < n; p += 512) {
            unsigned long long pk = src[p];
            int bin = (int)(pk >> 51);
            if (bin > tb) {
                int q = atomicAdd(&s_cA, 1);
                if (q < K) a[q] = pk;
            } else if (bin == tb) {
                int q = atomicAdd(&s_cE, 1);
                if (q < EQCAP) se[q] = pk;
            }
        }
    }
    __syncthreads();

    int mA = s_cA; if (mA > K) mA = K;
    int nE = s_cE; if (nE > EQCAP) nE = EQCAP;
    int take = K - mA; if (take > nE) take = nE;

    // ties: top 'take' by (score desc, idx asc) == largest packed
    for (int e = tid; e < nE; e += 512) {
        unsigned long long mine = se[e];
        int r = 0;
        for (int q = 0; q < nE; ++q) r += (se[q] > mine) ? 1 : 0;
        if (r < take) a[mA + r] = mine;
    }
    __syncthreads();

    int M = mA + take;                           // == K normally

    float* score_out = out;
    float* k_out     = out + B * K;
    float* c_out     = out + 2 * B * K;
    float* w_out     = out + 4 * B * K;

    if (tid < M) {
        unsigned long long mine = a[tid];
        int r = 0;
        for (int q = 0; q < M; ++q) r += (a[q] > mine) ? 1 : 0;

        int fi  = (int)(~(unsigned)(mine & 0xffffffffu));
        float sc = __uint_as_float((unsigned)(mine >> 32));
        int kk  = fi % C;
        int rem = fi / C;
        int jj  = rem % W;
        int ii  = rem / W;
        const float* p = y + ((size_t)((b * H + ii) * W + jj)) * CP;
        float whx = 4.0f * (expf(p[C])     - 1.0f);
        float why = 4.0f * (expf(p[C + 1]) - 1.0f);
        float cx  = 4.0f * (float)jj + p[C + 2];
        float cy  = 4.0f * (float)ii + p[C + 3];

        score_out[b * K + r] = sc;
        k_out[b * K + r]     = (float)kk;
        c_out[(b * K + r) * 2 + 0] = cx;
        c_out[(b * K + r) * 2 + 1] = cy;
        w_out[(b * K + r) * 2 + 0] = whx;
        w_out[(b * K + r) * 2 + 1] = why;
    }

    for (int r = M + tid; r < K; r += 512) {     // degenerate pad only
        score_out[b * K + r] = 0.0f;
        k_out[b * K + r]     = 0.0f;
        c_out[(b * K + r) * 2 + 0] = 0.0f;
        c_out[(b * K + r) * 2 + 1] = 0.0f;
        w_out[(b * K + r) * 2 + 0] = 0.0f;
        w_out[(b * K + r) * 2 + 1] = 0.0f;
    }

    __syncthreads();
    if (tid == 0) g_pcnt[b * 16] = 0ull;
}

extern "C" void kernel_launch(void* const* d_in, const int* in_sizes, int n_in,
                              void* d_out, int out_size) {
    const float* yp = (const float*)d_in[0];
    float* out = (float*)d_out;

    int total = B * 20 * (H / VR) * (W / JS);    // 819,200 threads
    peaks_kernel<<<total / 256, 256>>>(yp);
    select_kernel<<<B, 512>>>(yp, out);
}